// round 14
// baseline (speedup 1.0000x reference)
#include <cuda_runtime.h>
#include <cuda_fp16.h>
#include <cstdint>
#include <math.h>

// ---------------- problem dims ----------------------------------------------
#define B_DIM   4096
#define S_DIM   16
#define O_DIM   8
#define J_DIM   32
#define HID     240
#define OUT_HID 512
#define JB      (J_DIM * B_DIM)      // 131072
#define KPAD    256

// ---------------- scratch (device globals; zero-initialized at load) --------
__device__ float g_gh[3 * HID];
__device__ float g_bperm[768];
__device__ float g_xpred[B_DIM * S_DIM];
__device__ float g_inno[B_DIM * O_DIM];
__device__ float g_xin[B_DIM * HID];

__device__ __half g_A1[(size_t)JB * KPAD];        // (xin*mask1) fp16; pads stay 0
__device__ __half g_A2[(size_t)JB * KPAD];        // h_new fp16; pads stay 0
__device__ __half g_O1[(size_t)JB * OUT_HID];     // o1 fp16
__device__ __half g_Wp[768 * KPAD];               // permuted W_ih fp16; pads stay 0
__device__ __half g_Wo1[512 * KPAD];              // pads stay 0
__device__ __half g_Wo2[128 * 512];

// ---------------- helpers ----------------------------------------------------
__device__ __forceinline__ uint32_t smem_u32(const void* p) {
    uint32_t a;
    asm("{ .reg .u64 t; cvta.to.shared.u64 t, %1; cvt.u32.u64 %0, t; }" : "=r"(a) : "l"(p));
    return a;
}
__device__ __forceinline__ void ldsm4(uint32_t* r, uint32_t addr) {
    asm volatile("ldmatrix.sync.aligned.m8n8.x4.shared.b16 {%0,%1,%2,%3}, [%4];"
                 : "=r"(r[0]), "=r"(r[1]), "=r"(r[2]), "=r"(r[3]) : "r"(addr));
}
__device__ __forceinline__ void mma16816(float* c, const uint32_t* a, const uint32_t* b) {
    asm volatile(
        "mma.sync.aligned.m16n8k16.row.col.f32.f16.f16.f32 "
        "{%0,%1,%2,%3}, {%4,%5,%6,%7}, {%8,%9}, {%0,%1,%2,%3};"
        : "+f"(c[0]), "+f"(c[1]), "+f"(c[2]), "+f"(c[3])
        : "r"(a[0]), "r"(a[1]), "r"(a[2]), "r"(a[3]), "r"(b[0]), "r"(b[1]));
}
__device__ __forceinline__ void cpasync16(uint32_t dst, const void* src) {
    asm volatile("cp.async.cg.shared.global [%0], [%1], 16;" :: "r"(dst), "l"(src));
}
__device__ __forceinline__ float fsig(float x) {
    float e, r;
    asm("ex2.approx.ftz.f32 %0, %1;" : "=f"(e) : "f"(-x * 1.4426950408889634f));
    asm("rcp.approx.ftz.f32 %0, %1;" : "=f"(r) : "f"(1.0f + e));
    return r;
}
__device__ __forceinline__ float ftanh_(float x) { return 2.0f * fsig(2.0f * x) - 1.0f; }

// ---------------- K0: gh + permuted bias + reg scalar (one block) ------------
// bperm chunk layout: 6 chunks of [r(40) | z(40) | n(40) | pad(8)]
__global__ void ghb_kernel(const float* __restrict__ W_hh, const float* __restrict__ b_hh,
                           const float* __restrict__ h_init, const float* __restrict__ b_ih,
                           float* __restrict__ out) {
    __shared__ float sgh[3 * HID];
    int n = threadIdx.x;
    if (n < 3 * HID) {
        float acc = b_hh[n];
        const float* w = W_hh + n * HID;
#pragma unroll 8
        for (int k = 0; k < HID; k++) acc = fmaf(h_init[k], w[k], acc);
        g_gh[n] = acc;
        sgh[n] = acc;
    }
    __syncthreads();
    if (n < 768) {
        int c = n >> 7, w = n & 127;
        float v = 0.f;
        if (w < 120) {
            int gate = w / 40, t = w % 40;
            int orig = gate * 240 + c * 40 + t;
            v = b_ih[orig] + (gate < 2 ? sgh[orig] : 0.f);
        }
        g_bperm[n] = v;
    }
    if (n == 0) {
        const float p1 = 0.5f, p2 = 0.65f;
        out[2 * B_DIM * S_DIM] =
            -(p1 * logf(p1) + (1.0f - p1) * logf(1.0f - p1))
            - (p2 * logf(p2) + (1.0f - p2) * logf(1.0f - p2));
    }
}

// ---------------- K1: per-b prep --------------------------------------------
__global__ void prep_kernel(const float* __restrict__ y_t, const float* __restrict__ xprev,
                            const float* __restrict__ F, const float* __restrict__ H,
                            const float* __restrict__ W_fc, const float* __restrict__ b_fc) {
    int b = blockIdx.x;
    int t = threadIdx.x;
    __shared__ float xp[S_DIM], si[S_DIM], inn[O_DIM];
    if (t < S_DIM) {
        float acc = 0.f;
        const float* fr = F + t * S_DIM;
#pragma unroll
        for (int k = 0; k < S_DIM; k++) acc = fmaf(xprev[b * S_DIM + k], fr[k], acc);
        xp[t] = acc;
        si[t] = xprev[b * S_DIM + t] - acc;
        g_xpred[b * S_DIM + t] = acc;
    }
    __syncthreads();
    if (t < O_DIM) {
        float acc = 0.f;
        const float* hr = H + t * S_DIM;
#pragma unroll
        for (int s = 0; s < S_DIM; s++) acc = fmaf(xp[s], hr[s], acc);
        float iv = y_t[b * O_DIM + t] - acc;
        inn[t] = iv;
        g_inno[b * O_DIM + t] = iv;
    }
    __syncthreads();
    if (t < HID) {
        const float* w = W_fc + t * 48;
        float acc = b_fc[t];
#pragma unroll
        for (int s = 0; s < S_DIM; s++) acc = fmaf(si[s], w[s], acc);
#pragma unroll
        for (int o = 0; o < O_DIM; o++) acc = fmaf(inn[o], w[16 + o] + w[40 + o], acc);
        g_xin[b * HID + t] = fmaxf(acc, 0.0f);
    }
}

// ---------------- weight conversion (permuted Wih, fp16; skip pads) ----------
__global__ void convW_kernel(const float* __restrict__ W_ih,
                             const float* __restrict__ W_o1,
                             const float* __restrict__ W_o2) {
    int g = blockIdx.x * blockDim.x + threadIdx.x;
    const int N1 = 768 * KPAD, N2 = 512 * KPAD, N3 = 128 * 512;
    if (g < N1) {
        int n = g >> 8, k = g & 255;
        int c = n >> 7, w = n & 127;
        if (w < 120 && k < 240) {
            int gate = w / 40, t = w % 40;
            g_Wp[g] = __float2half_rn(W_ih[(gate * 240 + c * 40 + t) * 240 + k]);
        }
    } else if (g < N1 + N2) {
        int i = g - N1;
        int k = i & 255;
        if (k < 240)
            g_Wo1[i] = __float2half_rn(W_o1[(i >> 8) * 240 + k]);
    } else if (g < N1 + N2 + N3) {
        int i = g - N1 - N2;
        g_Wo2[i] = __float2half_rn(W_o2[i]);
    }
}

// ---------------- conv1: A1 = fp16(xin * mask1), 8 elems/thread --------------
__global__ void conv1_kernel(const float* __restrict__ u1) {
    int g = blockIdx.x * blockDim.x + threadIdx.x;   // row*30 + c8
    if (g >= JB * 30) return;
    int row = g / 30, c8 = g - row * 30;
    int k = c8 * 8;
    int b = row & (B_DIM - 1);
    float4 x0 = *reinterpret_cast<const float4*>(g_xin + b * HID + k);
    float4 x1 = *reinterpret_cast<const float4*>(g_xin + b * HID + k + 4);
    float4 u0 = *reinterpret_cast<const float4*>(u1 + (size_t)row * HID + k);
    float4 u1v = *reinterpret_cast<const float4*>(u1 + (size_t)row * HID + k + 4);
    __half hh[8];
    hh[0] = __float2half_rn((u0.x > 0.5f) ? 2.0f * x0.x : 0.f);
    hh[1] = __float2half_rn((u0.y > 0.5f) ? 2.0f * x0.y : 0.f);
    hh[2] = __float2half_rn((u0.z > 0.5f) ? 2.0f * x0.z : 0.f);
    hh[3] = __float2half_rn((u0.w > 0.5f) ? 2.0f * x0.w : 0.f);
    hh[4] = __float2half_rn((u1v.x > 0.5f) ? 2.0f * x1.x : 0.f);
    hh[5] = __float2half_rn((u1v.y > 0.5f) ? 2.0f * x1.y : 0.f);
    hh[6] = __float2half_rn((u1v.z > 0.5f) ? 2.0f * x1.z : 0.f);
    hh[7] = __float2half_rn((u1v.w > 0.5f) ? 2.0f * x1.w : 0.f);
    *reinterpret_cast<uint4*>(g_A1 + (size_t)row * KPAD + k) = *reinterpret_cast<uint4*>(hh);
}

// ---------------- streaming fp16 GEMM, 3-stage ring, 2 CTAs/SM (R9) ----------
// 128x128 block, BK=32, ONE barrier per kt, 8 warps (2m x 4n), warp tile 64x32.
// Stage: 2 arrays (A, B) x 128 rows x 80B stride.
// MODE 1: permuted chunk -> GRU epilogue -> g_A2 fp16  [K=256, grid(6,1024)]
// MODE 2: O1 = fp16(relu(A2@Wo1^T+b)*mask2(u2))        [K=256, grid(4,1024)]
// MODE 3: ens = xpred + (O1@Wo2^T + b2).inno           [K=512, grid(1,1024)]
#define ARR_BYTES   10240          // 128 * 80
#define STAGE_BYTES 20480          // 2 * ARR_BYTES
#define GEMM_SMEM   (3 * STAGE_BYTES + 512)

template <int MODE>
__global__ __launch_bounds__(256, 2)
void gemm_mma(const float* __restrict__ aux1,   // M2: b_out1, M3: b_out2
              const float* __restrict__ aux2,   // M1: h_init, M2: u2
              float* __restrict__ ens) {        // M3 only
    constexpr int KA = (MODE == 3) ? 512 : KPAD;
    constexpr int NKT = KA / 32;

    const __half* pA = (MODE == 1) ? g_A1 : ((MODE == 2) ? g_A2 : g_O1);
    const __half* pB = (MODE == 1) ? g_Wp : ((MODE == 2) ? g_Wo1 : g_Wo2);

    extern __shared__ char smem[];
    float* biasS = reinterpret_cast<float*>(smem + 3 * STAGE_BYTES);
    const uint32_t sb = smem_u32(smem);
    const int tid = threadIdx.x;
    const int lane = tid & 31, wid = tid >> 5;
    const int wm = wid & 1, wn = wid >> 1;
    const int m0 = blockIdx.y * 128, n0 = blockIdx.x * 128;

    if (tid < 128)
        biasS[tid] = (MODE == 1) ? g_bperm[n0 + tid] : aux1[n0 + tid];

    const int r0c = tid >> 2, c0c = tid & 3;
    const int r1c = (tid + 256) >> 2;

    auto prefetch = [&](int kt) {
        uint32_t stage = sb + (kt % 3) * STAGE_BYTES;
        int kh = kt * 32;
#pragma unroll
        for (int q = 0; q < 2; q++) {
            int r = q ? r1c : r0c;
            uint32_t d = stage + r * 80 + c0c * 16;
            size_t ao = (size_t)(m0 + r) * KA + kh + c0c * 8;
            size_t bo = (MODE == 3) ? ((size_t)r * KA + kh + c0c * 8)
                                    : ((size_t)(n0 + r) * KA + kh + c0c * 8);
            cpasync16(d,             pA + ao);
            cpasync16(d + ARR_BYTES, pB + bo);
        }
    };

    float c[4][4][4];
#pragma unroll
    for (int i = 0; i < 4; i++)
#pragma unroll
        for (int j = 0; j < 4; j++)
#pragma unroll
            for (int q = 0; q < 4; q++) c[i][j][q] = 0.f;

    prefetch(0);
    asm volatile("cp.async.commit_group;");
    prefetch(1);
    asm volatile("cp.async.commit_group;");

    for (int kt = 0; kt < NKT; kt++) {
        if (kt == NKT - 1) asm volatile("cp.async.wait_group 0;");
        else               asm volatile("cp.async.wait_group 1;");
        __syncthreads();
        if (kt + 2 < NKT) {
            prefetch(kt + 2);
            asm volatile("cp.async.commit_group;");
        }
        uint32_t stage = sb + (kt % 3) * STAGE_BYTES;
#pragma unroll
        for (int s = 0; s < 2; s++) {
            uint32_t bh[2][4];
            uint32_t bcol = (((lane >> 3) & 1) << 4) + s * 32;
#pragma unroll
            for (int np = 0; np < 2; np++) {
                int rowB = wn * 32 + np * 16 + ((lane >> 4) << 3) + (lane & 7);
                ldsm4(bh[np], stage + ARR_BYTES + rowB * 80 + bcol);
            }
            uint32_t acol = ((lane >> 4) << 4) + s * 32;
#pragma unroll
            for (int mt = 0; mt < 4; mt++) {
                uint32_t ah[4];
                int rowA = wm * 64 + mt * 16 + (lane & 15);
                ldsm4(ah, stage + rowA * 80 + acol);
#pragma unroll
                for (int nt = 0; nt < 4; nt++)
                    mma16816(c[mt][nt], ah, &bh[nt >> 1][(nt & 1) * 2]);
            }
        }
    }
    __syncthreads();   // protect stage area before epilogue aliasing (MODE 1)

    // ---------------- epilogues ----------------
    const int g = lane >> 2, tg = lane & 3;
    if (MODE == 1) {
        // GRU over chunk cols [r(40)|z(40)|n(40)]: SMEM exchange in stage area
        const int ch = blockIdx.x;
        float* scr = reinterpret_cast<float*>(smem);  // 64 x 128 fp32 = 32KB
#pragma unroll
        for (int p = 0; p < 2; p++) {
            if (wm == p) {
#pragma unroll
                for (int mt = 0; mt < 4; mt++)
#pragma unroll
                    for (int half = 0; half < 2; half++) {
                        int lr = mt * 16 + g + half * 8;
#pragma unroll
                        for (int nt = 0; nt < 4; nt++) {
                            int colL = wn * 32 + nt * 8 + tg * 2;
                            scr[lr * 128 + colL] = c[mt][nt][2 * half + 0];
                            scr[lr * 128 + colL + 1] = c[mt][nt][2 * half + 1];
                        }
                    }
            }
            __syncthreads();
#pragma unroll
            for (int it = 0; it < 5; it++) {
                int item = tid + 256 * it;          // [0,1280) = 64 rows x 20 pairs
                int lr = item / 20, h2 = (item - lr * 20) * 2;
                int row = m0 + p * 64 + lr;
                __half hh[2];
#pragma unroll
                for (int e = 0; e < 2; e++) {
                    int h = h2 + e;
                    int hp = ch * 40 + h;
                    float r = fsig(scr[lr * 128 + h] + biasS[h]);
                    float z = fsig(scr[lr * 128 + 40 + h] + biasS[40 + h]);
                    float nn = ftanh_(scr[lr * 128 + 80 + h] + biasS[80 + h]
                                      + r * g_gh[480 + hp]);
                    float hv = (1.0f - z) * nn + z * aux2[hp];
                    hh[e] = __float2half_rn(hv);
                }
                *reinterpret_cast<uint32_t*>(g_A2 + (size_t)row * KPAD + ch * 40 + h2) =
                    *reinterpret_cast<uint32_t*>(hh);
            }
            __syncthreads();
        }
    } else if (MODE == 2) {
#pragma unroll
        for (int mt = 0; mt < 4; mt++)
#pragma unroll
            for (int half = 0; half < 2; half++) {
                int row = m0 + wm * 64 + mt * 16 + g + half * 8;
#pragma unroll
                for (int nt = 0; nt < 4; nt++) {
                    int colL = wn * 32 + nt * 8 + tg * 2;
                    int col = n0 + colL;
                    float2 u = *reinterpret_cast<const float2*>(
                        aux2 + (size_t)row * OUT_HID + col);
                    float t0 = fmaxf(c[mt][nt][2 * half + 0] + biasS[colL], 0.f);
                    float t1 = fmaxf(c[mt][nt][2 * half + 1] + biasS[colL + 1], 0.f);
                    __half hh[2];
                    hh[0] = __float2half_rn((u.x > 0.65f) ? t0 * (1.0f / 0.35f) : 0.f);
                    hh[1] = __float2half_rn((u.y > 0.65f) ? t1 * (1.0f / 0.35f) : 0.f);
                    *reinterpret_cast<uint32_t*>(g_O1 + (size_t)row * OUT_HID + col) =
                        *reinterpret_cast<uint32_t*>(hh);
                }
            }
    } else {  // MODE 3: n = s*8+o; warp covers s = wn*4+nt, o = tg*2,+1
#pragma unroll
        for (int mt = 0; mt < 4; mt++) {
#pragma unroll
            for (int half = 0; half < 2; half++) {
                int row = m0 + wm * 64 + mt * 16 + g + half * 8;
                int b = row & (B_DIM - 1);
                int j = row >> 12;
                float2 iv = *reinterpret_cast<const float2*>(g_inno + b * O_DIM + tg * 2);
#pragma unroll
                for (int nt = 0; nt < 4; nt++) {
                    int colL = wn * 32 + nt * 8 + tg * 2;
                    float v = (c[mt][nt][2 * half + 0] + biasS[colL]) * iv.x
                            + (c[mt][nt][2 * half + 1] + biasS[colL + 1]) * iv.y;
                    v += __shfl_xor_sync(0xffffffffu, v, 1);
                    v += __shfl_xor_sync(0xffffffffu, v, 2);
                    if (tg == 0) {
                        int s = wn * 4 + nt;
                        ens[(size_t)b * (J_DIM * S_DIM) + j * S_DIM + s] =
                            g_xpred[b * S_DIM + s] + v;
                    }
                }
            }
        }
    }
}

// ---------------- mean / unbiased var over J --------------------------------
__global__ void reduce_kernel(const float* __restrict__ ens, float* __restrict__ out) {
    int idx = blockIdx.x * blockDim.x + threadIdx.x;
    if (idx >= B_DIM * S_DIM) return;
    int b = idx >> 4, s = idx & 15;
    const float* p = ens + (size_t)b * (J_DIM * S_DIM) + s;
    float v[J_DIM], sum = 0.f;
#pragma unroll
    for (int j = 0; j < J_DIM; j++) { v[j] = p[j * S_DIM]; sum += v[j]; }
    float mean = sum * (1.0f / J_DIM);
    float var = 0.f;
#pragma unroll
    for (int j = 0; j < J_DIM; j++) { float d = v[j] - mean; var = fmaf(d, d, var); }
    out[idx] = mean;
    out[B_DIM * S_DIM + idx] = var * (1.0f / (J_DIM - 1));
}

// ---------------- launcher --------------------------------------------------
extern "C" void kernel_launch(void* const* d_in, const int* in_sizes, int n_in,
                              void* d_out, int out_size) {
    const float* y_t    = (const float*)d_in[0];
    const float* xprev  = (const float*)d_in[1];
    const float* F      = (const float*)d_in[2];
    const float* H      = (const float*)d_in[3];
    const float* W_fc   = (const float*)d_in[4];
    const float* b_fc   = (const float*)d_in[5];
    const float* W_ih   = (const float*)d_in[6];
    const float* W_hh   = (const float*)d_in[7];
    const float* b_ih   = (const float*)d_in[8];
    const float* b_hh   = (const float*)d_in[9];
    const float* W_out1 = (const float*)d_in[10];
    const float* b_out1 = (const float*)d_in[11];
    const float* W_out2 = (const float*)d_in[12];
    const float* b_out2 = (const float*)d_in[13];
    const float* h_init = (const float*)d_in[14];
    const float* u1     = (const float*)d_in[15];
    const float* u2     = (const float*)d_in[16];

    float* out = (float*)d_out;
    float* ens = out + 2 * B_DIM * S_DIM + 1;

    cudaFuncSetAttribute((const void*)gemm_mma<1>, cudaFuncAttributeMaxDynamicSharedMemorySize, GEMM_SMEM);
    cudaFuncSetAttribute((const void*)gemm_mma<2>, cudaFuncAttributeMaxDynamicSharedMemorySize, GEMM_SMEM);
    cudaFuncSetAttribute((const void*)gemm_mma<3>, cudaFuncAttributeMaxDynamicSharedMemorySize, GEMM_SMEM);

    ghb_kernel<<<1, 768>>>(W_hh, b_hh, h_init, b_ih, out);
    prep_kernel<<<B_DIM, 256>>>(y_t, xprev, F, H, W_fc, b_fc);
    convW_kernel<<<(768 * KPAD + 512 * KPAD + 128 * 512 + 255) / 256, 256>>>(W_ih, W_out1, W_out2);
    conv1_kernel<<<(JB * 30 + 255) / 256, 256>>>(u1);

    // G1 + GRU fused epilogue -> g_A2
    gemm_mma<1><<<dim3(6, JB / 128), 256, GEMM_SMEM>>>(nullptr, h_init, nullptr);

    // G2: O1 = fp16(relu(A2 @ Wo1^T + b) * mask2)
    gemm_mma<2><<<dim3(4, JB / 128), 256, GEMM_SMEM>>>(b_out1, u2, nullptr);

    // G3: ensemble = xpred + (O1 @ Wo2^T + b2) . inno
    gemm_mma<3><<<dim3(1, JB / 128), 256, GEMM_SMEM>>>(b_out2, nullptr, ens);

    reduce_kernel<<<(B_DIM * S_DIM) / 256, 256>>>(ens, out);
}

// round 15
// speedup vs baseline: 1.0487x; 1.0487x over previous
#include <cuda_runtime.h>
#include <cuda_fp16.h>
#include <cstdint>
#include <math.h>

// ---------------- problem dims ----------------------------------------------
#define B_DIM   4096
#define S_DIM   16
#define O_DIM   8
#define J_DIM   32
#define HID     240
#define OUT_HID 512
#define JB      (J_DIM * B_DIM)      // 131072
#define KPAD    256

// ---------------- scratch (device globals) ----------------------------------
__device__ float g_gh[3 * HID];
__device__ float g_bperm[768];
__device__ float g_xpred[B_DIM * S_DIM];
__device__ float g_inno[B_DIM * O_DIM];
__device__ float g_xin[B_DIM * HID];

__device__ __half g_A1[(size_t)JB * KPAD];        // (xin*mask1) fp16
__device__ __half g_A2[(size_t)JB * KPAD];        // h_new fp16
__device__ __half g_O1[(size_t)JB * OUT_HID];     // o1 fp16
__device__ __half g_Wp[768 * KPAD];               // permuted W_ih fp16
__device__ __half g_Wo1[512 * KPAD];
__device__ __half g_Wo2[128 * 512];

// ---------------- helpers ----------------------------------------------------
__device__ __forceinline__ uint32_t smem_u32(const void* p) {
    uint32_t a;
    asm("{ .reg .u64 t; cvta.to.shared.u64 t, %1; cvt.u32.u64 %0, t; }" : "=r"(a) : "l"(p));
    return a;
}
__device__ __forceinline__ void ldsm4(uint32_t* r, uint32_t addr) {
    asm volatile("ldmatrix.sync.aligned.m8n8.x4.shared.b16 {%0,%1,%2,%3}, [%4];"
                 : "=r"(r[0]), "=r"(r[1]), "=r"(r[2]), "=r"(r[3]) : "r"(addr));
}
__device__ __forceinline__ void mma16816(float* c, const uint32_t* a, const uint32_t* b) {
    asm volatile(
        "mma.sync.aligned.m16n8k16.row.col.f32.f16.f16.f32 "
        "{%0,%1,%2,%3}, {%4,%5,%6,%7}, {%8,%9}, {%0,%1,%2,%3};"
        : "+f"(c[0]), "+f"(c[1]), "+f"(c[2]), "+f"(c[3])
        : "r"(a[0]), "r"(a[1]), "r"(a[2]), "r"(a[3]), "r"(b[0]), "r"(b[1]));
}
__device__ __forceinline__ void cpasync16(uint32_t dst, const void* src) {
    asm volatile("cp.async.cg.shared.global [%0], [%1], 16;" :: "r"(dst), "l"(src));
}
__device__ __forceinline__ float fsig(float x) {
    float e, r;
    asm("ex2.approx.ftz.f32 %0, %1;" : "=f"(e) : "f"(-x * 1.4426950408889634f));
    asm("rcp.approx.ftz.f32 %0, %1;" : "=f"(r) : "f"(1.0f + e));
    return r;
}
__device__ __forceinline__ float ftanh_(float x) { return 2.0f * fsig(2.0f * x) - 1.0f; }
__device__ __forceinline__ void hsplit(float v, __half& h, __half& l) {
    h = __float2half_rn(v);
    l = __float2half_rn(v - __half2float(h));
}

// ---------------- K0: gh + reg scalar ---------------------------------------
__global__ void gh_kernel(const float* __restrict__ W_hh, const float* __restrict__ b_hh,
                          const float* __restrict__ h_init, float* __restrict__ out) {
    int n = blockIdx.x * blockDim.x + threadIdx.x;
    if (n < 3 * HID) {
        float acc = b_hh[n];
        const float* w = W_hh + n * HID;
#pragma unroll 8
        for (int k = 0; k < HID; k++) acc = fmaf(h_init[k], w[k], acc);
        g_gh[n] = acc;
    }
    if (n == 0) {
        const float p1 = 0.5f, p2 = 0.65f;
        out[2 * B_DIM * S_DIM] =
            -(p1 * logf(p1) + (1.0f - p1) * logf(1.0f - p1))
            - (p2 * logf(p2) + (1.0f - p2) * logf(1.0f - p2));
    }
}

// permuted combined bias: chunk layout [r(40) | z(40) | n(40) | pad(8)] x 6
__global__ void bprep_kernel(const float* __restrict__ b_ih) {
    int n = blockIdx.x * blockDim.x + threadIdx.x;
    if (n >= 768) return;
    int c = n >> 7, w = n & 127;
    float v = 0.f;
    if (w < 120) {
        int gate = w / 40, t = w % 40;
        int orig = gate * 240 + c * 40 + t;
        v = b_ih[orig] + (gate < 2 ? g_gh[orig] : 0.f);
    }
    g_bperm[n] = v;
}

// ---------------- K1: per-b prep --------------------------------------------
__global__ void prep_kernel(const float* __restrict__ y_t, const float* __restrict__ xprev,
                            const float* __restrict__ F, const float* __restrict__ H,
                            const float* __restrict__ W_fc, const float* __restrict__ b_fc) {
    int b = blockIdx.x;
    int t = threadIdx.x;
    __shared__ float xp[S_DIM], si[S_DIM], inn[O_DIM];
    if (t < S_DIM) {
        float acc = 0.f;
        const float* fr = F + t * S_DIM;
#pragma unroll
        for (int k = 0; k < S_DIM; k++) acc = fmaf(xprev[b * S_DIM + k], fr[k], acc);
        xp[t] = acc;
        si[t] = xprev[b * S_DIM + t] - acc;
        g_xpred[b * S_DIM + t] = acc;
    }
    __syncthreads();
    if (t < O_DIM) {
        float acc = 0.f;
        const float* hr = H + t * S_DIM;
#pragma unroll
        for (int s = 0; s < S_DIM; s++) acc = fmaf(xp[s], hr[s], acc);
        float iv = y_t[b * O_DIM + t] - acc;
        inn[t] = iv;
        g_inno[b * O_DIM + t] = iv;
    }
    __syncthreads();
    if (t < HID) {
        const float* w = W_fc + t * 48;
        float acc = b_fc[t];
#pragma unroll
        for (int s = 0; s < S_DIM; s++) acc = fmaf(si[s], w[s], acc);
#pragma unroll
        for (int o = 0; o < O_DIM; o++) acc = fmaf(inn[o], w[16 + o] + w[40 + o], acc);
        g_xin[b * HID + t] = fmaxf(acc, 0.0f);
    }
}

// ---------------- weight conversion (permuted Wih, fp16) ---------------------
__global__ void convW_kernel(const float* __restrict__ W_ih,
                             const float* __restrict__ W_o1,
                             const float* __restrict__ W_o2) {
    int g = blockIdx.x * blockDim.x + threadIdx.x;
    const int N1 = 768 * KPAD, N2 = 512 * KPAD, N3 = 128 * 512;
    if (g < N1) {
        int n = g >> 8, k = g & 255;
        int c = n >> 7, w = n & 127;
        float v = 0.f;
        if (w < 120 && k < 240) {
            int gate = w / 40, t = w % 40;
            v = W_ih[(gate * 240 + c * 40 + t) * 240 + k];
        }
        g_Wp[g] = __float2half_rn(v);
    } else if (g < N1 + N2) {
        int i = g - N1;
        int k = i & 255;
        g_Wo1[i] = __float2half_rn((k < 240) ? W_o1[(i >> 8) * 240 + k] : 0.f);
    } else if (g < N1 + N2 + N3) {
        int i = g - N1 - N2;
        g_Wo2[i] = __float2half_rn(W_o2[i]);
    }
}

// ---------------- conv1: A1 = fp16(xin * mask1) ------------------------------
__global__ void conv1_kernel(const float* __restrict__ u1) {
    int g = blockIdx.x * blockDim.x + threadIdx.x;   // row*64 + k4
    if (g >= JB * 64) return;
    int row = g >> 6, k4 = g & 63;
    __half hh[4];
    if (k4 < 60) {
        int b = row & (B_DIM - 1);
        float4 x = *reinterpret_cast<const float4*>(g_xin + b * HID + 4 * k4);
        float4 u = *reinterpret_cast<const float4*>(u1 + (size_t)row * HID + 4 * k4);
        hh[0] = __float2half_rn((u.x > 0.5f) ? 2.0f * x.x : 0.f);
        hh[1] = __float2half_rn((u.y > 0.5f) ? 2.0f * x.y : 0.f);
        hh[2] = __float2half_rn((u.z > 0.5f) ? 2.0f * x.z : 0.f);
        hh[3] = __float2half_rn((u.w > 0.5f) ? 2.0f * x.w : 0.f);
    } else {
#pragma unroll
        for (int e = 0; e < 4; e++) hh[e] = __float2half_rn(0.f);
    }
    *reinterpret_cast<uint2*>(g_A1 + (size_t)row * KPAD + 4 * k4) = *reinterpret_cast<uint2*>(hh);
}

// ---------------- streaming fp16 GEMM, 3-stage ring, 2 CTAs/SM ---------------
// 128x128 block, BK=32, ONE barrier per kt, 8 warps (2m x 4n), warp tile 64x32.
// Stage: 2 arrays (A, B) x 128 rows x 80B stride.
// MODE 1: permuted chunk -> GRU epilogue -> g_A2 fp16  [K=256, grid(6,1024)]
// MODE 2: O1 = fp16(relu(A2@Wo1^T+b)*mask2)            [K=256, grid(4,1024)]
// MODE 3: ens = xpred + (O1@Wo2^T + b2).inno           [K=512, grid(1,1024)]
#define ARR_BYTES   10240          // 128 * 80
#define STAGE_BYTES 20480          // 2 * ARR_BYTES
#define GEMM_SMEM   (3 * STAGE_BYTES + 512)

template <int MODE>
__global__ __launch_bounds__(256, 2)
void gemm_mma(const float* __restrict__ aux1,   // M2: b_out1, M3: b_out2
              const float* __restrict__ aux2,   // M1: h_init, M2: u2
              float* __restrict__ ens) {        // M3 only
    constexpr int KA = (MODE == 3) ? 512 : KPAD;
    constexpr int NKT = KA / 32;

    const __half* pA = (MODE == 1) ? g_A1 : ((MODE == 2) ? g_A2 : g_O1);
    const __half* pB = (MODE == 1) ? g_Wp : ((MODE == 2) ? g_Wo1 : g_Wo2);

    extern __shared__ char smem[];
    float* biasS = reinterpret_cast<float*>(smem + 3 * STAGE_BYTES);
    const uint32_t sb = smem_u32(smem);
    const int tid = threadIdx.x;
    const int lane = tid & 31, wid = tid >> 5;
    const int wm = wid & 1, wn = wid >> 1;
    const int m0 = blockIdx.y * 128, n0 = blockIdx.x * 128;

    if (tid < 128)
        biasS[tid] = (MODE == 1) ? g_bperm[n0 + tid] : aux1[n0 + tid];

    const int r0c = tid >> 2, c0c = tid & 3;
    const int r1c = (tid + 256) >> 2;

    auto prefetch = [&](int kt) {
        uint32_t stage = sb + (kt % 3) * STAGE_BYTES;
        int kh = kt * 32;
#pragma unroll
        for (int q = 0; q < 2; q++) {
            int r = q ? r1c : r0c;
            uint32_t d = stage + r * 80 + c0c * 16;
            size_t ao = (size_t)(m0 + r) * KA + kh + c0c * 8;
            size_t bo = (MODE == 3) ? ((size_t)r * KA + kh + c0c * 8)
                                    : ((size_t)(n0 + r) * KA + kh + c0c * 8);
            cpasync16(d,             pA + ao);
            cpasync16(d + ARR_BYTES, pB + bo);
        }
    };

    float c[4][4][4];
#pragma unroll
    for (int i = 0; i < 4; i++)
#pragma unroll
        for (int j = 0; j < 4; j++)
#pragma unroll
            for (int q = 0; q < 4; q++) c[i][j][q] = 0.f;

    prefetch(0);
    asm volatile("cp.async.commit_group;");
    prefetch(1);
    asm volatile("cp.async.commit_group;");

    for (int kt = 0; kt < NKT; kt++) {
        if (kt == NKT - 1) asm volatile("cp.async.wait_group 0;");
        else               asm volatile("cp.async.wait_group 1;");
        __syncthreads();
        if (kt + 2 < NKT) {
            prefetch(kt + 2);
            asm volatile("cp.async.commit_group;");
        }
        uint32_t stage = sb + (kt % 3) * STAGE_BYTES;
#pragma unroll
        for (int s = 0; s < 2; s++) {
            uint32_t bh[2][4];
            uint32_t bcol = (((lane >> 3) & 1) << 4) + s * 32;
#pragma unroll
            for (int np = 0; np < 2; np++) {
                int rowB = wn * 32 + np * 16 + ((lane >> 4) << 3) + (lane & 7);
                ldsm4(bh[np], stage + ARR_BYTES + rowB * 80 + bcol);
            }
            uint32_t acol = ((lane >> 4) << 4) + s * 32;
#pragma unroll
            for (int mt = 0; mt < 4; mt++) {
                uint32_t ah[4];
                int rowA = wm * 64 + mt * 16 + (lane & 15);
                ldsm4(ah, stage + rowA * 80 + acol);
#pragma unroll
                for (int nt = 0; nt < 4; nt++)
                    mma16816(c[mt][nt], ah, &bh[nt >> 1][(nt & 1) * 2]);
            }
        }
    }
    __syncthreads();   // protect stage area before epilogue aliasing (MODE 1)

    // ---------------- epilogues ----------------
    const int g = lane >> 2, tg = lane & 3;
    if (MODE == 1) {
        // GRU over chunk cols [r(40)|z(40)|n(40)]: SMEM exchange in stage area
        const int ch = blockIdx.x;
        float* scr = reinterpret_cast<float*>(smem);  // 64 x 128 fp32 = 32KB
#pragma unroll
        for (int p = 0; p < 2; p++) {
            if (wm == p) {
#pragma unroll
                for (int mt = 0; mt < 4; mt++)
#pragma unroll
                    for (int half = 0; half < 2; half++) {
                        int lr = mt * 16 + g + half * 8;
#pragma unroll
                        for (int nt = 0; nt < 4; nt++) {
                            int colL = wn * 32 + nt * 8 + tg * 2;
                            scr[lr * 128 + colL] = c[mt][nt][2 * half + 0];
                            scr[lr * 128 + colL + 1] = c[mt][nt][2 * half + 1];
                        }
                    }
            }
            __syncthreads();
#pragma unroll
            for (int it = 0; it < 5; it++) {
                int item = tid + 256 * it;          // [0,1280) = 64 rows x 20 pairs
                int lr = item / 20, h2 = (item - lr * 20) * 2;
                int row = m0 + p * 64 + lr;
                __half hh[2];
#pragma unroll
                for (int e = 0; e < 2; e++) {
                    int h = h2 + e;
                    int hp = ch * 40 + h;
                    float r = fsig(scr[lr * 128 + h] + biasS[h]);
                    float z = fsig(scr[lr * 128 + 40 + h] + biasS[40 + h]);
                    float nn = ftanh_(scr[lr * 128 + 80 + h] + biasS[80 + h]
                                      + r * g_gh[480 + hp]);
                    float hv = (1.0f - z) * nn + z * aux2[hp];
                    hh[e] = __float2half_rn(hv);
                }
                *reinterpret_cast<uint32_t*>(g_A2 + (size_t)row * KPAD + ch * 40 + h2) =
                    *reinterpret_cast<uint32_t*>(hh);
            }
            __syncthreads();
        }
    } else if (MODE == 2) {
#pragma unroll
        for (int mt = 0; mt < 4; mt++)
#pragma unroll
            for (int half = 0; half < 2; half++) {
                int row = m0 + wm * 64 + mt * 16 + g + half * 8;
#pragma unroll
                for (int nt = 0; nt < 4; nt++) {
                    int colL = wn * 32 + nt * 8 + tg * 2;
                    int col = n0 + colL;
                    float2 u = *reinterpret_cast<const float2*>(
                        aux2 + (size_t)row * OUT_HID + col);
                    float t0 = fmaxf(c[mt][nt][2 * half + 0] + biasS[colL], 0.f);
                    float t1 = fmaxf(c[mt][nt][2 * half + 1] + biasS[colL + 1], 0.f);
                    __half hh[2];
                    hh[0] = __float2half_rn((u.x > 0.65f) ? t0 * (1.0f / 0.35f) : 0.f);
                    hh[1] = __float2half_rn((u.y > 0.65f) ? t1 * (1.0f / 0.35f) : 0.f);
                    *reinterpret_cast<uint32_t*>(g_O1 + (size_t)row * OUT_HID + col) =
                        *reinterpret_cast<uint32_t*>(hh);
                }
            }
    } else {  // MODE 3: n = s*8+o; warp covers s = wn*4+nt, o = tg*2,+1
#pragma unroll
        for (int mt = 0; mt < 4; mt++) {
#pragma unroll
            for (int half = 0; half < 2; half++) {
                int row = m0 + wm * 64 + mt * 16 + g + half * 8;
                int b = row & (B_DIM - 1);
                int j = row >> 12;
                float2 iv = *reinterpret_cast<const float2*>(g_inno + b * O_DIM + tg * 2);
#pragma unroll
                for (int nt = 0; nt < 4; nt++) {
                    int colL = wn * 32 + nt * 8 + tg * 2;
                    float v = (c[mt][nt][2 * half + 0] + biasS[colL]) * iv.x
                            + (c[mt][nt][2 * half + 1] + biasS[colL + 1]) * iv.y;
                    v += __shfl_xor_sync(0xffffffffu, v, 1);
                    v += __shfl_xor_sync(0xffffffffu, v, 2);
                    if (tg == 0) {
                        int s = wn * 4 + nt;
                        ens[(size_t)b * (J_DIM * S_DIM) + j * S_DIM + s] =
                            g_xpred[b * S_DIM + s] + v;
                    }
                }
            }
        }
    }
}

// ---------------- mean / unbiased var over J --------------------------------
__global__ void reduce_kernel(const float* __restrict__ ens, float* __restrict__ out) {
    int idx = blockIdx.x * blockDim.x + threadIdx.x;
    if (idx >= B_DIM * S_DIM) return;
    int b = idx >> 4, s = idx & 15;
    const float* p = ens + (size_t)b * (J_DIM * S_DIM) + s;
    float v[J_DIM], sum = 0.f;
#pragma unroll
    for (int j = 0; j < J_DIM; j++) { v[j] = p[j * S_DIM]; sum += v[j]; }
    float mean = sum * (1.0f / J_DIM);
    float var = 0.f;
#pragma unroll
    for (int j = 0; j < J_DIM; j++) { float d = v[j] - mean; var = fmaf(d, d, var); }
    out[idx] = mean;
    out[B_DIM * S_DIM + idx] = var * (1.0f / (J_DIM - 1));
}

// ---------------- launcher --------------------------------------------------
extern "C" void kernel_launch(void* const* d_in, const int* in_sizes, int n_in,
                              void* d_out, int out_size) {
    const float* y_t    = (const float*)d_in[0];
    const float* xprev  = (const float*)d_in[1];
    const float* F      = (const float*)d_in[2];
    const float* H      = (const float*)d_in[3];
    const float* W_fc   = (const float*)d_in[4];
    const float* b_fc   = (const float*)d_in[5];
    const float* W_ih   = (const float*)d_in[6];
    const float* W_hh   = (const float*)d_in[7];
    const float* b_ih   = (const float*)d_in[8];
    const float* b_hh   = (const float*)d_in[9];
    const float* W_out1 = (const float*)d_in[10];
    const float* b_out1 = (const float*)d_in[11];
    const float* W_out2 = (const float*)d_in[12];
    const float* b_out2 = (const float*)d_in[13];
    const float* h_init = (const float*)d_in[14];
    const float* u1     = (const float*)d_in[15];
    const float* u2     = (const float*)d_in[16];

    float* out = (float*)d_out;
    float* ens = out + 2 * B_DIM * S_DIM + 1;

    cudaFuncSetAttribute((const void*)gemm_mma<1>, cudaFuncAttributeMaxDynamicSharedMemorySize, GEMM_SMEM);
    cudaFuncSetAttribute((const void*)gemm_mma<2>, cudaFuncAttributeMaxDynamicSharedMemorySize, GEMM_SMEM);
    cudaFuncSetAttribute((const void*)gemm_mma<3>, cudaFuncAttributeMaxDynamicSharedMemorySize, GEMM_SMEM);

    gh_kernel<<<3, 256>>>(W_hh, b_hh, h_init, out);
    bprep_kernel<<<3, 256>>>(b_ih);
    prep_kernel<<<B_DIM, 256>>>(y_t, xprev, F, H, W_fc, b_fc);
    convW_kernel<<<(768 * KPAD + 512 * KPAD + 128 * 512 + 255) / 256, 256>>>(W_ih, W_out1, W_out2);
    conv1_kernel<<<(JB * 64) / 256, 256>>>(u1);

    // G1 + GRU fused epilogue -> g_A2
    gemm_mma<1><<<dim3(6, JB / 128), 256, GEMM_SMEM>>>(nullptr, h_init, nullptr);

    // G2: O1 = fp16(relu(A2 @ Wo1^T + b) * mask2)
    gemm_mma<2><<<dim3(4, JB / 128), 256, GEMM_SMEM>>>(b_out1, u2, nullptr);

    // G3: ensemble = xpred + (O1 @ Wo2^T + b2) . inno
    gemm_mma<3><<<dim3(1, JB / 128), 256, GEMM_SMEM>>>(b_out2, nullptr, ens);

    reduce_kernel<<<(B_DIM * S_DIM) / 256, 256>>>(ens, out);
}

// round 16
// speedup vs baseline: 1.0491x; 1.0004x over previous
#include <cuda_runtime.h>
#include <cuda_fp16.h>
#include <cstdint>
#include <math.h>

// ---------------- problem dims ----------------------------------------------
#define B_DIM   4096
#define S_DIM   16
#define O_DIM   8
#define J_DIM   32
#define HID     240
#define OUT_HID 512
#define JB      (J_DIM * B_DIM)      // 131072
#define KPAD    256

// ---------------- scratch (device globals) ----------------------------------
__device__ float g_gh[3 * HID];
__device__ float g_bperm[768];
__device__ float g_xpred[B_DIM * S_DIM];
__device__ float g_inno[B_DIM * O_DIM];
__device__ float g_xin[B_DIM * HID];

__device__ __half g_A1[(size_t)JB * KPAD];        // (xin*mask1) fp16
__device__ __half g_A2[(size_t)JB * KPAD];        // h_new fp16
__device__ __half g_O1[(size_t)JB * OUT_HID];     // o1 fp16
__device__ __half g_Wp[768 * KPAD];               // permuted W_ih fp16
__device__ __half g_Wo1[512 * KPAD];
__device__ __half g_Wo2[128 * 512];

// ---------------- helpers ----------------------------------------------------
__device__ __forceinline__ uint32_t smem_u32(const void* p) {
    uint32_t a;
    asm("{ .reg .u64 t; cvta.to.shared.u64 t, %1; cvt.u32.u64 %0, t; }" : "=r"(a) : "l"(p));
    return a;
}
__device__ __forceinline__ void ldsm4(uint32_t* r, uint32_t addr) {
    asm volatile("ldmatrix.sync.aligned.m8n8.x4.shared.b16 {%0,%1,%2,%3}, [%4];"
                 : "=r"(r[0]), "=r"(r[1]), "=r"(r[2]), "=r"(r[3]) : "r"(addr));
}
__device__ __forceinline__ void mma16816(float* c, const uint32_t* a, const uint32_t* b) {
    asm volatile(
        "mma.sync.aligned.m16n8k16.row.col.f32.f16.f16.f32 "
        "{%0,%1,%2,%3}, {%4,%5,%6,%7}, {%8,%9}, {%0,%1,%2,%3};"
        : "+f"(c[0]), "+f"(c[1]), "+f"(c[2]), "+f"(c[3])
        : "r"(a[0]), "r"(a[1]), "r"(a[2]), "r"(a[3]), "r"(b[0]), "r"(b[1]));
}
__device__ __forceinline__ void cpasync16(uint32_t dst, const void* src) {
    asm volatile("cp.async.cg.shared.global [%0], [%1], 16;" :: "r"(dst), "l"(src));
}
__device__ __forceinline__ float fsig(float x) {
    float e, r;
    asm("ex2.approx.ftz.f32 %0, %1;" : "=f"(e) : "f"(-x * 1.4426950408889634f));
    asm("rcp.approx.ftz.f32 %0, %1;" : "=f"(r) : "f"(1.0f + e));
    return r;
}
__device__ __forceinline__ float ftanh_(float x) { return 2.0f * fsig(2.0f * x) - 1.0f; }
__device__ __forceinline__ void hsplit(float v, __half& h, __half& l) {
    h = __float2half_rn(v);
    l = __float2half_rn(v - __half2float(h));
}

// ---------------- K0: gh + reg scalar ---------------------------------------
__global__ void gh_kernel(const float* __restrict__ W_hh, const float* __restrict__ b_hh,
                          const float* __restrict__ h_init, float* __restrict__ out) {
    int n = blockIdx.x * blockDim.x + threadIdx.x;
    if (n < 3 * HID) {
        float acc = b_hh[n];
        const float* w = W_hh + n * HID;
#pragma unroll 8
        for (int k = 0; k < HID; k++) acc = fmaf(h_init[k], w[k], acc);
        g_gh[n] = acc;
    }
    if (n == 0) {
        const float p1 = 0.5f, p2 = 0.65f;
        out[2 * B_DIM * S_DIM] =
            -(p1 * logf(p1) + (1.0f - p1) * logf(1.0f - p1))
            - (p2 * logf(p2) + (1.0f - p2) * logf(1.0f - p2));
    }
}

// permuted combined bias: chunk layout [r(40) | z(40) | n(40) | pad(8)] x 6
__global__ void bprep_kernel(const float* __restrict__ b_ih) {
    int n = blockIdx.x * blockDim.x + threadIdx.x;
    if (n >= 768) return;
    int c = n >> 7, w = n & 127;
    float v = 0.f;
    if (w < 120) {
        int gate = w / 40, t = w % 40;
        int orig = gate * 240 + c * 40 + t;
        v = b_ih[orig] + (gate < 2 ? g_gh[orig] : 0.f);
    }
    g_bperm[n] = v;
}

// ---------------- K1: per-b prep --------------------------------------------
__global__ void prep_kernel(const float* __restrict__ y_t, const float* __restrict__ xprev,
                            const float* __restrict__ F, const float* __restrict__ H,
                            const float* __restrict__ W_fc, const float* __restrict__ b_fc) {
    int b = blockIdx.x;
    int t = threadIdx.x;
    __shared__ float xp[S_DIM], si[S_DIM], inn[O_DIM];
    if (t < S_DIM) {
        float acc = 0.f;
        const float* fr = F + t * S_DIM;
#pragma unroll
        for (int k = 0; k < S_DIM; k++) acc = fmaf(xprev[b * S_DIM + k], fr[k], acc);
        xp[t] = acc;
        si[t] = xprev[b * S_DIM + t] - acc;
        g_xpred[b * S_DIM + t] = acc;
    }
    __syncthreads();
    if (t < O_DIM) {
        float acc = 0.f;
        const float* hr = H + t * S_DIM;
#pragma unroll
        for (int s = 0; s < S_DIM; s++) acc = fmaf(xp[s], hr[s], acc);
        float iv = y_t[b * O_DIM + t] - acc;
        inn[t] = iv;
        g_inno[b * O_DIM + t] = iv;
    }
    __syncthreads();
    if (t < HID) {
        const float* w = W_fc + t * 48;
        float acc = b_fc[t];
#pragma unroll
        for (int s = 0; s < S_DIM; s++) acc = fmaf(si[s], w[s], acc);
#pragma unroll
        for (int o = 0; o < O_DIM; o++) acc = fmaf(inn[o], w[16 + o] + w[40 + o], acc);
        g_xin[b * HID + t] = fmaxf(acc, 0.0f);
    }
}

// ---------------- weight conversion (permuted Wih, fp16) ---------------------
__global__ void convW_kernel(const float* __restrict__ W_ih,
                             const float* __restrict__ W_o1,
                             const float* __restrict__ W_o2) {
    int g = blockIdx.x * blockDim.x + threadIdx.x;
    const int N1 = 768 * KPAD, N2 = 512 * KPAD, N3 = 128 * 512;
    if (g < N1) {
        int n = g >> 8, k = g & 255;
        int c = n >> 7, w = n & 127;
        float v = 0.f;
        if (w < 120 && k < 240) {
            int gate = w / 40, t = w % 40;
            v = W_ih[(gate * 240 + c * 40 + t) * 240 + k];
        }
        g_Wp[g] = __float2half_rn(v);
    } else if (g < N1 + N2) {
        int i = g - N1;
        int k = i & 255;
        g_Wo1[i] = __float2half_rn((k < 240) ? W_o1[(i >> 8) * 240 + k] : 0.f);
    } else if (g < N1 + N2 + N3) {
        int i = g - N1 - N2;
        g_Wo2[i] = __float2half_rn(W_o2[i]);
    }
}

// ---------------- conv1: A1 = fp16(xin * mask1) ------------------------------
__global__ void conv1_kernel(const float* __restrict__ u1) {
    int g = blockIdx.x * blockDim.x + threadIdx.x;   // row*64 + k4
    if (g >= JB * 64) return;
    int row = g >> 6, k4 = g & 63;
    __half hh[4];
    if (k4 < 60) {
        int b = row & (B_DIM - 1);
        float4 x = *reinterpret_cast<const float4*>(g_xin + b * HID + 4 * k4);
        float4 u = *reinterpret_cast<const float4*>(u1 + (size_t)row * HID + 4 * k4);
        hh[0] = __float2half_rn((u.x > 0.5f) ? 2.0f * x.x : 0.f);
        hh[1] = __float2half_rn((u.y > 0.5f) ? 2.0f * x.y : 0.f);
        hh[2] = __float2half_rn((u.z > 0.5f) ? 2.0f * x.z : 0.f);
        hh[3] = __float2half_rn((u.w > 0.5f) ? 2.0f * x.w : 0.f);
    } else {
#pragma unroll
        for (int e = 0; e < 4; e++) hh[e] = __float2half_rn(0.f);
    }
    *reinterpret_cast<uint2*>(g_A1 + (size_t)row * KPAD + 4 * k4) = *reinterpret_cast<uint2*>(hh);
}

// ---------------- streaming fp16 GEMM, 3-stage ring, 2 CTAs/SM ---------------
// 128x128 block, BK=32, ONE barrier per kt, 8 warps (2m x 4n), warp tile 64x32.
// Stage: 2 arrays (A, B) x 128 rows x 80B stride.
// MODE 1: permuted chunk -> GRU epilogue -> g_A2 fp16  [K=256, grid(6,1024)]
// MODE 2: O1 = fp16(relu(A2@Wo1^T+b)*mask2)            [K=256, grid(4,1024)]
// MODE 3: ens = xpred + (O1@Wo2^T + b2).inno           [K=512, grid(1,1024)]
#define ARR_BYTES   10240          // 128 * 80
#define STAGE_BYTES 20480          // 2 * ARR_BYTES
#define GEMM_SMEM   (3 * STAGE_BYTES + 512)

template <int MODE>
__global__ __launch_bounds__(256, 2)
void gemm_mma(const float* __restrict__ aux1,   // M2: b_out1, M3: b_out2
              const float* __restrict__ aux2,   // M1: h_init, M2: u2
              float* __restrict__ ens) {        // M3 only
    constexpr int KA = (MODE == 3) ? 512 : KPAD;
    constexpr int NKT = KA / 32;

    const __half* pA = (MODE == 1) ? g_A1 : ((MODE == 2) ? g_A2 : g_O1);
    const __half* pB = (MODE == 1) ? g_Wp : ((MODE == 2) ? g_Wo1 : g_Wo2);

    extern __shared__ char smem[];
    float* biasS = reinterpret_cast<float*>(smem + 3 * STAGE_BYTES);
    const uint32_t sb = smem_u32(smem);
    const int tid = threadIdx.x;
    const int lane = tid & 31, wid = tid >> 5;
    const int wm = wid & 1, wn = wid >> 1;
    const int m0 = blockIdx.y * 128, n0 = blockIdx.x * 128;

    if (tid < 128)
        biasS[tid] = (MODE == 1) ? g_bperm[n0 + tid] : aux1[n0 + tid];

    const int r0c = tid >> 2, c0c = tid & 3;
    const int r1c = (tid + 256) >> 2;

    auto prefetch = [&](int kt) {
        uint32_t stage = sb + (kt % 3) * STAGE_BYTES;
        int kh = kt * 32;
#pragma unroll
        for (int q = 0; q < 2; q++) {
            int r = q ? r1c : r0c;
            uint32_t d = stage + r * 80 + c0c * 16;
            size_t ao = (size_t)(m0 + r) * KA + kh + c0c * 8;
            size_t bo = (MODE == 3) ? ((size_t)r * KA + kh + c0c * 8)
                                    : ((size_t)(n0 + r) * KA + kh + c0c * 8);
            cpasync16(d,             pA + ao);
            cpasync16(d + ARR_BYTES, pB + bo);
        }
    };

    float c[4][4][4];
#pragma unroll
    for (int i = 0; i < 4; i++)
#pragma unroll
        for (int j = 0; j < 4; j++)
#pragma unroll
            for (int q = 0; q < 4; q++) c[i][j][q] = 0.f;

    prefetch(0);
    asm volatile("cp.async.commit_group;");
    prefetch(1);
    asm volatile("cp.async.commit_group;");

    for (int kt = 0; kt < NKT; kt++) {
        if (kt == NKT - 1) asm volatile("cp.async.wait_group 0;");
        else               asm volatile("cp.async.wait_group 1;");
        __syncthreads();
        if (kt + 2 < NKT) {
            prefetch(kt + 2);
            asm volatile("cp.async.commit_group;");
        }
        uint32_t stage = sb + (kt % 3) * STAGE_BYTES;
#pragma unroll
        for (int s = 0; s < 2; s++) {
            uint32_t bh[2][4];
            uint32_t bcol = (((lane >> 3) & 1) << 4) + s * 32;
#pragma unroll
            for (int np = 0; np < 2; np++) {
                int rowB = wn * 32 + np * 16 + ((lane >> 4) << 3) + (lane & 7);
                ldsm4(bh[np], stage + ARR_BYTES + rowB * 80 + bcol);
            }
            uint32_t acol = ((lane >> 4) << 4) + s * 32;
#pragma unroll
            for (int mt = 0; mt < 4; mt++) {
                uint32_t ah[4];
                int rowA = wm * 64 + mt * 16 + (lane & 15);
                ldsm4(ah, stage + rowA * 80 + acol);
#pragma unroll
                for (int nt = 0; nt < 4; nt++)
                    mma16816(c[mt][nt], ah, &bh[nt >> 1][(nt & 1) * 2]);
            }
        }
    }
    __syncthreads();   // protect stage area before epilogue aliasing (MODE 1)

    // ---------------- epilogues ----------------
    const int g = lane >> 2, tg = lane & 3;
    if (MODE == 1) {
        // GRU over chunk cols [r(40)|z(40)|n(40)]: SMEM exchange in stage area
        const int ch = blockIdx.x;
        float* scr = reinterpret_cast<float*>(smem);  // 64 x 128 fp32 = 32KB
#pragma unroll
        for (int p = 0; p < 2; p++) {
            if (wm == p) {
#pragma unroll
                for (int mt = 0; mt < 4; mt++)
#pragma unroll
                    for (int half = 0; half < 2; half++) {
                        int lr = mt * 16 + g + half * 8;
#pragma unroll
                        for (int nt = 0; nt < 4; nt++) {
                            int colL = wn * 32 + nt * 8 + tg * 2;
                            scr[lr * 128 + colL] = c[mt][nt][2 * half + 0];
                            scr[lr * 128 + colL + 1] = c[mt][nt][2 * half + 1];
                        }
                    }
            }
            __syncthreads();
#pragma unroll
            for (int it = 0; it < 5; it++) {
                int item = tid + 256 * it;          // [0,1280) = 64 rows x 20 pairs
                int lr = item / 20, h2 = (item - lr * 20) * 2;
                int row = m0 + p * 64 + lr;
                __half hh[2];
#pragma unroll
                for (int e = 0; e < 2; e++) {
                    int h = h2 + e;
                    int hp = ch * 40 + h;
                    float r = fsig(scr[lr * 128 + h] + biasS[h]);
                    float z = fsig(scr[lr * 128 + 40 + h] + biasS[40 + h]);
                    float nn = ftanh_(scr[lr * 128 + 80 + h] + biasS[80 + h]
                                      + r * g_gh[480 + hp]);
                    float hv = (1.0f - z) * nn + z * aux2[hp];
                    hh[e] = __float2half_rn(hv);
                }
                *reinterpret_cast<uint32_t*>(g_A2 + (size_t)row * KPAD + ch * 40 + h2) =
                    *reinterpret_cast<uint32_t*>(hh);
            }
            __syncthreads();
        }
    } else if (MODE == 2) {
#pragma unroll
        for (int mt = 0; mt < 4; mt++)
#pragma unroll
            for (int half = 0; half < 2; half++) {
                int row = m0 + wm * 64 + mt * 16 + g + half * 8;
#pragma unroll
                for (int nt = 0; nt < 4; nt++) {
                    int colL = wn * 32 + nt * 8 + tg * 2;
                    int col = n0 + colL;
                    float2 u = *reinterpret_cast<const float2*>(
                        aux2 + (size_t)row * OUT_HID + col);
                    float t0 = fmaxf(c[mt][nt][2 * half + 0] + biasS[colL], 0.f);
                    float t1 = fmaxf(c[mt][nt][2 * half + 1] + biasS[colL + 1], 0.f);
                    __half hh[2];
                    hh[0] = __float2half_rn((u.x > 0.65f) ? t0 * (1.0f / 0.35f) : 0.f);
                    hh[1] = __float2half_rn((u.y > 0.65f) ? t1 * (1.0f / 0.35f) : 0.f);
                    *reinterpret_cast<uint32_t*>(g_O1 + (size_t)row * OUT_HID + col) =
                        *reinterpret_cast<uint32_t*>(hh);
                }
            }
    } else {  // MODE 3: n = s*8+o; warp covers s = wn*4+nt, o = tg*2,+1
#pragma unroll
        for (int mt = 0; mt < 4; mt++) {
#pragma unroll
            for (int half = 0; half < 2; half++) {
                int row = m0 + wm * 64 + mt * 16 + g + half * 8;
                int b = row & (B_DIM - 1);
                int j = row >> 12;
                float2 iv = *reinterpret_cast<const float2*>(g_inno + b * O_DIM + tg * 2);
#pragma unroll
                for (int nt = 0; nt < 4; nt++) {
                    int colL = wn * 32 + nt * 8 + tg * 2;
                    float v = (c[mt][nt][2 * half + 0] + biasS[colL]) * iv.x
                            + (c[mt][nt][2 * half + 1] + biasS[colL + 1]) * iv.y;
                    v += __shfl_xor_sync(0xffffffffu, v, 1);
                    v += __shfl_xor_sync(0xffffffffu, v, 2);
                    if (tg == 0) {
                        int s = wn * 4 + nt;
                        ens[(size_t)b * (J_DIM * S_DIM) + j * S_DIM + s] =
                            g_xpred[b * S_DIM + s] + v;
                    }
                }
            }
        }
    }
}

// ---------------- mean / unbiased var over J --------------------------------
__global__ void reduce_kernel(const float* __restrict__ ens, float* __restrict__ out) {
    int idx = blockIdx.x * blockDim.x + threadIdx.x;
    if (idx >= B_DIM * S_DIM) return;
    int b = idx >> 4, s = idx & 15;
    const float* p = ens + (size_t)b * (J_DIM * S_DIM) + s;
    float v[J_DIM], sum = 0.f;
#pragma unroll
    for (int j = 0; j < J_DIM; j++) { v[j] = p[j * S_DIM]; sum += v[j]; }
    float mean = sum * (1.0f / J_DIM);
    float var = 0.f;
#pragma unroll
    for (int j = 0; j < J_DIM; j++) { float d = v[j] - mean; var = fmaf(d, d, var); }
    out[idx] = mean;
    out[B_DIM * S_DIM + idx] = var * (1.0f / (J_DIM - 1));
}

// ---------------- launcher --------------------------------------------------
extern "C" void kernel_launch(void* const* d_in, const int* in_sizes, int n_in,
                              void* d_out, int out_size) {
    const float* y_t    = (const float*)d_in[0];
    const float* xprev  = (const float*)d_in[1];
    const float* F      = (const float*)d_in[2];
    const float* H      = (const float*)d_in[3];
    const float* W_fc   = (const float*)d_in[4];
    const float* b_fc   = (const float*)d_in[5];
    const float* W_ih   = (const float*)d_in[6];
    const float* W_hh   = (const float*)d_in[7];
    const float* b_ih   = (const float*)d_in[8];
    const float* b_hh   = (const float*)d_in[9];
    const float* W_out1 = (const float*)d_in[10];
    const float* b_out1 = (const float*)d_in[11];
    const float* W_out2 = (const float*)d_in[12];
    const float* b_out2 = (const float*)d_in[13];
    const float* h_init = (const float*)d_in[14];
    const float* u1     = (const float*)d_in[15];
    const float* u2     = (const float*)d_in[16];

    float* out = (float*)d_out;
    float* ens = out + 2 * B_DIM * S_DIM + 1;

    cudaFuncSetAttribute((const void*)gemm_mma<1>, cudaFuncAttributeMaxDynamicSharedMemorySize, GEMM_SMEM);
    cudaFuncSetAttribute((const void*)gemm_mma<2>, cudaFuncAttributeMaxDynamicSharedMemorySize, GEMM_SMEM);
    cudaFuncSetAttribute((const void*)gemm_mma<3>, cudaFuncAttributeMaxDynamicSharedMemorySize, GEMM_SMEM);

    gh_kernel<<<3, 256>>>(W_hh, b_hh, h_init, out);
    bprep_kernel<<<3, 256>>>(b_ih);
    prep_kernel<<<B_DIM, 256>>>(y_t, xprev, F, H, W_fc, b_fc);
    convW_kernel<<<(768 * KPAD + 512 * KPAD + 128 * 512 + 255) / 256, 256>>>(W_ih, W_out1, W_out2);
    conv1_kernel<<<(JB * 64) / 256, 256>>>(u1);

    // G1 + GRU fused epilogue -> g_A2
    gemm_mma<1><<<dim3(6, JB / 128), 256, GEMM_SMEM>>>(nullptr, h_init, nullptr);

    // G2: O1 = fp16(relu(A2 @ Wo1^T + b) * mask2)
    gemm_mma<2><<<dim3(4, JB / 128), 256, GEMM_SMEM>>>(b_out1, u2, nullptr);

    // G3: ensemble = xpred + (O1 @ Wo2^T + b2) . inno
    gemm_mma<3><<<dim3(1, JB / 128), 256, GEMM_SMEM>>>(b_out2, nullptr, ens);

    reduce_kernel<<<(B_DIM * S_DIM) / 256, 256>>>(ens, out);
}

// round 17
// speedup vs baseline: 1.0604x; 1.0107x over previous
#include <cuda_runtime.h>
#include <cuda_fp16.h>
#include <cstdint>
#include <math.h>

// ---------------- problem dims ----------------------------------------------
#define B_DIM   4096
#define S_DIM   16
#define O_DIM   8
#define J_DIM   32
#define HID     240
#define OUT_HID 512
#define JB      (J_DIM * B_DIM)      // 131072
#define KPAD    256

// ---------------- scratch (device globals) ----------------------------------
__device__ float g_gh[3 * HID];
__device__ float g_bperm[768];
__device__ float g_xpred[B_DIM * S_DIM];
__device__ float g_inno[B_DIM * O_DIM];
__device__ float g_xin[B_DIM * HID];

__device__ __half g_A1[(size_t)JB * KPAD];        // (xin*mask1) fp16
__device__ __half g_A2[(size_t)JB * KPAD];        // h_new fp16
__device__ __half g_O1[(size_t)JB * OUT_HID];     // o1 fp16
__device__ __half g_Wp[768 * KPAD];               // permuted W_ih fp16
__device__ __half g_Wo1[512 * KPAD];
__device__ __half g_Wo2[128 * 512];

// ---------------- helpers ----------------------------------------------------
__device__ __forceinline__ uint32_t smem_u32(const void* p) {
    uint32_t a;
    asm("{ .reg .u64 t; cvta.to.shared.u64 t, %1; cvt.u32.u64 %0, t; }" : "=r"(a) : "l"(p));
    return a;
}
__device__ __forceinline__ void ldsm4(uint32_t* r, uint32_t addr) {
    asm volatile("ldmatrix.sync.aligned.m8n8.x4.shared.b16 {%0,%1,%2,%3}, [%4];"
                 : "=r"(r[0]), "=r"(r[1]), "=r"(r[2]), "=r"(r[3]) : "r"(addr));
}
__device__ __forceinline__ void mma16816(float* c, const uint32_t* a, const uint32_t* b) {
    asm volatile(
        "mma.sync.aligned.m16n8k16.row.col.f32.f16.f16.f32 "
        "{%0,%1,%2,%3}, {%4,%5,%6,%7}, {%8,%9}, {%0,%1,%2,%3};"
        : "+f"(c[0]), "+f"(c[1]), "+f"(c[2]), "+f"(c[3])
        : "r"(a[0]), "r"(a[1]), "r"(a[2]), "r"(a[3]), "r"(b[0]), "r"(b[1]));
}
__device__ __forceinline__ void cpasync16(uint32_t dst, const void* src) {
    asm volatile("cp.async.cg.shared.global [%0], [%1], 16;" :: "r"(dst), "l"(src));
}
__device__ __forceinline__ float fsig(float x) {
    float e, r;
    asm("ex2.approx.ftz.f32 %0, %1;" : "=f"(e) : "f"(-x * 1.4426950408889634f));
    asm("rcp.approx.ftz.f32 %0, %1;" : "=f"(r) : "f"(1.0f + e));
    return r;
}
__device__ __forceinline__ float ftanh_(float x) { return 2.0f * fsig(2.0f * x) - 1.0f; }
__device__ __forceinline__ void hsplit(float v, __half& h, __half& l) {
    h = __float2half_rn(v);
    l = __float2half_rn(v - __half2float(h));
}

// ---------------- K0: gh + reg scalar ---------------------------------------
__global__ void gh_kernel(const float* __restrict__ W_hh, const float* __restrict__ b_hh,
                          const float* __restrict__ h_init, float* __restrict__ out) {
    int n = blockIdx.x * blockDim.x + threadIdx.x;
    if (n < 3 * HID) {
        float acc = b_hh[n];
        const float* w = W_hh + n * HID;
#pragma unroll 8
        for (int k = 0; k < HID; k++) acc = fmaf(h_init[k], w[k], acc);
        g_gh[n] = acc;
    }
    if (n == 0) {
        const float p1 = 0.5f, p2 = 0.65f;
        out[2 * B_DIM * S_DIM] =
            -(p1 * logf(p1) + (1.0f - p1) * logf(1.0f - p1))
            - (p2 * logf(p2) + (1.0f - p2) * logf(1.0f - p2));
    }
}

// permuted combined bias: chunk layout [r(40) | z(40) | n(40) | pad(8)] x 6
__global__ void bprep_kernel(const float* __restrict__ b_ih) {
    int n = blockIdx.x * blockDim.x + threadIdx.x;
    if (n >= 768) return;
    int c = n >> 7, w = n & 127;
    float v = 0.f;
    if (w < 120) {
        int gate = w / 40, t = w % 40;
        int orig = gate * 240 + c * 40 + t;
        v = b_ih[orig] + (gate < 2 ? g_gh[orig] : 0.f);
    }
    g_bperm[n] = v;
}

// ---------------- K1: per-b prep --------------------------------------------
__global__ void prep_kernel(const float* __restrict__ y_t, const float* __restrict__ xprev,
                            const float* __restrict__ F, const float* __restrict__ H,
                            const float* __restrict__ W_fc, const float* __restrict__ b_fc) {
    int b = blockIdx.x;
    int t = threadIdx.x;
    __shared__ float xp[S_DIM], si[S_DIM], inn[O_DIM];
    if (t < S_DIM) {
        float acc = 0.f;
        const float* fr = F + t * S_DIM;
#pragma unroll
        for (int k = 0; k < S_DIM; k++) acc = fmaf(xprev[b * S_DIM + k], fr[k], acc);
        xp[t] = acc;
        si[t] = xprev[b * S_DIM + t] - acc;
        g_xpred[b * S_DIM + t] = acc;
    }
    __syncthreads();
    if (t < O_DIM) {
        float acc = 0.f;
        const float* hr = H + t * S_DIM;
#pragma unroll
        for (int s = 0; s < S_DIM; s++) acc = fmaf(xp[s], hr[s], acc);
        float iv = y_t[b * O_DIM + t] - acc;
        inn[t] = iv;
        g_inno[b * O_DIM + t] = iv;
    }
    __syncthreads();
    if (t < HID) {
        const float* w = W_fc + t * 48;
        float acc = b_fc[t];
#pragma unroll
        for (int s = 0; s < S_DIM; s++) acc = fmaf(si[s], w[s], acc);
#pragma unroll
        for (int o = 0; o < O_DIM; o++) acc = fmaf(inn[o], w[16 + o] + w[40 + o], acc);
        g_xin[b * HID + t] = fmaxf(acc, 0.0f);
    }
}

// ---------------- weight conversion (permuted Wih, fp16) ---------------------
__global__ void convW_kernel(const float* __restrict__ W_ih,
                             const float* __restrict__ W_o1,
                             const float* __restrict__ W_o2) {
    int g = blockIdx.x * blockDim.x + threadIdx.x;
    const int N1 = 768 * KPAD, N2 = 512 * KPAD, N3 = 128 * 512;
    if (g < N1) {
        int n = g >> 8, k = g & 255;
        int c = n >> 7, w = n & 127;
        float v = 0.f;
        if (w < 120 && k < 240) {
            int gate = w / 40, t = w % 40;
            v = W_ih[(gate * 240 + c * 40 + t) * 240 + k];
        }
        g_Wp[g] = __float2half_rn(v);
    } else if (g < N1 + N2) {
        int i = g - N1;
        int k = i & 255;
        g_Wo1[i] = __float2half_rn((k < 240) ? W_o1[(i >> 8) * 240 + k] : 0.f);
    } else if (g < N1 + N2 + N3) {
        int i = g - N1 - N2;
        g_Wo2[i] = __float2half_rn(W_o2[i]);
    }
}

// ---------------- conv1: A1 = fp16(xin * mask1), 8 elems/thread --------------
// row covered by 32 chunks of 8 cols; chunks 30-31 write zero pads (cols 240-255)
__global__ void conv1_kernel(const float* __restrict__ u1) {
    int g = blockIdx.x * blockDim.x + threadIdx.x;   // row*32 + c8
    if (g >= JB * 32) return;
    int row = g >> 5, c8 = g & 31;
    int k = c8 * 8;
    __half hh[8];
    if (k < 240) {
        int b = row & (B_DIM - 1);
        float4 x0 = *reinterpret_cast<const float4*>(g_xin + b * HID + k);
        float4 x1 = *reinterpret_cast<const float4*>(g_xin + b * HID + k + 4);
        float4 u0 = *reinterpret_cast<const float4*>(u1 + (size_t)row * HID + k);
        float4 u1v = *reinterpret_cast<const float4*>(u1 + (size_t)row * HID + k + 4);
        hh[0] = __float2half_rn((u0.x > 0.5f) ? 2.0f * x0.x : 0.f);
        hh[1] = __float2half_rn((u0.y > 0.5f) ? 2.0f * x0.y : 0.f);
        hh[2] = __float2half_rn((u0.z > 0.5f) ? 2.0f * x0.z : 0.f);
        hh[3] = __float2half_rn((u0.w > 0.5f) ? 2.0f * x0.w : 0.f);
        hh[4] = __float2half_rn((u1v.x > 0.5f) ? 2.0f * x1.x : 0.f);
        hh[5] = __float2half_rn((u1v.y > 0.5f) ? 2.0f * x1.y : 0.f);
        hh[6] = __float2half_rn((u1v.z > 0.5f) ? 2.0f * x1.z : 0.f);
        hh[7] = __float2half_rn((u1v.w > 0.5f) ? 2.0f * x1.w : 0.f);
    } else {
#pragma unroll
        for (int e = 0; e < 8; e++) hh[e] = __float2half_rn(0.f);
    }
    *reinterpret_cast<uint4*>(g_A1 + (size_t)row * KPAD + k) = *reinterpret_cast<uint4*>(hh);
}

// ---------------- streaming fp16 GEMM, 3-stage ring, 2 CTAs/SM ---------------
// 128x128 block, BK=32, ONE barrier per kt, 8 warps (2m x 4n), warp tile 64x32.
// Stage: 2 arrays (A, B) x 128 rows x 80B stride.
// MODE 1: permuted chunk -> GRU epilogue -> g_A2 fp16  [K=256, grid(6,1024)]
// MODE 2: O1 = fp16(relu(A2@Wo1^T+b)*mask2)            [K=256, grid(4,1024)]
// MODE 3: ens = xpred + (O1@Wo2^T + b2).inno           [K=512, grid(1,1024)]
#define ARR_BYTES   10240          // 128 * 80
#define STAGE_BYTES 20480          // 2 * ARR_BYTES
#define GEMM_SMEM   (3 * STAGE_BYTES + 512)

template <int MODE>
__global__ __launch_bounds__(256, 2)
void gemm_mma(const float* __restrict__ aux1,   // M2: b_out1, M3: b_out2
              const float* __restrict__ aux2,   // M1: h_init, M2: u2
              float* __restrict__ ens) {        // M3 only
    constexpr int KA = (MODE == 3) ? 512 : KPAD;
    constexpr int NKT = KA / 32;

    const __half* pA = (MODE == 1) ? g_A1 : ((MODE == 2) ? g_A2 : g_O1);
    const __half* pB = (MODE == 1) ? g_Wp : ((MODE == 2) ? g_Wo1 : g_Wo2);

    extern __shared__ char smem[];
    float* biasS = reinterpret_cast<float*>(smem + 3 * STAGE_BYTES);
    const uint32_t sb = smem_u32(smem);
    const int tid = threadIdx.x;
    const int lane = tid & 31, wid = tid >> 5;
    const int wm = wid & 1, wn = wid >> 1;
    const int m0 = blockIdx.y * 128, n0 = blockIdx.x * 128;

    if (tid < 128)
        biasS[tid] = (MODE == 1) ? g_bperm[n0 + tid] : aux1[n0 + tid];

    const int r0c = tid >> 2, c0c = tid & 3;
    const int r1c = (tid + 256) >> 2;

    auto prefetch = [&](int kt) {
        uint32_t stage = sb + (kt % 3) * STAGE_BYTES;
        int kh = kt * 32;
#pragma unroll
        for (int q = 0; q < 2; q++) {
            int r = q ? r1c : r0c;
            uint32_t d = stage + r * 80 + c0c * 16;
            size_t ao = (size_t)(m0 + r) * KA + kh + c0c * 8;
            size_t bo = (MODE == 3) ? ((size_t)r * KA + kh + c0c * 8)
                                    : ((size_t)(n0 + r) * KA + kh + c0c * 8);
            cpasync16(d,             pA + ao);
            cpasync16(d + ARR_BYTES, pB + bo);
        }
    };

    float c[4][4][4];
#pragma unroll
    for (int i = 0; i < 4; i++)
#pragma unroll
        for (int j = 0; j < 4; j++)
#pragma unroll
            for (int q = 0; q < 4; q++) c[i][j][q] = 0.f;

    prefetch(0);
    asm volatile("cp.async.commit_group;");
    prefetch(1);
    asm volatile("cp.async.commit_group;");

    for (int kt = 0; kt < NKT; kt++) {
        if (kt == NKT - 1) asm volatile("cp.async.wait_group 0;");
        else               asm volatile("cp.async.wait_group 1;");
        __syncthreads();
        if (kt + 2 < NKT) {
            prefetch(kt + 2);
            asm volatile("cp.async.commit_group;");
        }
        uint32_t stage = sb + (kt % 3) * STAGE_BYTES;
#pragma unroll
        for (int s = 0; s < 2; s++) {
            uint32_t bh[2][4];
            uint32_t bcol = (((lane >> 3) & 1) << 4) + s * 32;
#pragma unroll
            for (int np = 0; np < 2; np++) {
                int rowB = wn * 32 + np * 16 + ((lane >> 4) << 3) + (lane & 7);
                ldsm4(bh[np], stage + ARR_BYTES + rowB * 80 + bcol);
            }
            uint32_t acol = ((lane >> 4) << 4) + s * 32;
#pragma unroll
            for (int mt = 0; mt < 4; mt++) {
                uint32_t ah[4];
                int rowA = wm * 64 + mt * 16 + (lane & 15);
                ldsm4(ah, stage + rowA * 80 + acol);
#pragma unroll
                for (int nt = 0; nt < 4; nt++)
                    mma16816(c[mt][nt], ah, &bh[nt >> 1][(nt & 1) * 2]);
            }
        }
    }
    __syncthreads();   // protect stage area before epilogue aliasing (MODE 1)

    // ---------------- epilogues ----------------
    const int g = lane >> 2, tg = lane & 3;
    if (MODE == 1) {
        // GRU over chunk cols [r(40)|z(40)|n(40)]: SMEM exchange in stage area
        const int ch = blockIdx.x;
        float* scr = reinterpret_cast<float*>(smem);  // 64 x 128 fp32 = 32KB
#pragma unroll
        for (int p = 0; p < 2; p++) {
            if (wm == p) {
#pragma unroll
                for (int mt = 0; mt < 4; mt++)
#pragma unroll
                    for (int half = 0; half < 2; half++) {
                        int lr = mt * 16 + g + half * 8;
#pragma unroll
                        for (int nt = 0; nt < 4; nt++) {
                            int colL = wn * 32 + nt * 8 + tg * 2;
                            scr[lr * 128 + colL] = c[mt][nt][2 * half + 0];
                            scr[lr * 128 + colL + 1] = c[mt][nt][2 * half + 1];
                        }
                    }
            }
            __syncthreads();
#pragma unroll
            for (int it = 0; it < 5; it++) {
                int item = tid + 256 * it;          // [0,1280) = 64 rows x 20 pairs
                int lr = item / 20, h2 = (item - lr * 20) * 2;
                int row = m0 + p * 64 + lr;
                __half hh[2];
#pragma unroll
                for (int e = 0; e < 2; e++) {
                    int h = h2 + e;
                    int hp = ch * 40 + h;
                    float r = fsig(scr[lr * 128 + h] + biasS[h]);
                    float z = fsig(scr[lr * 128 + 40 + h] + biasS[40 + h]);
                    float nn = ftanh_(scr[lr * 128 + 80 + h] + biasS[80 + h]
                                      + r * g_gh[480 + hp]);
                    float hv = (1.0f - z) * nn + z * aux2[hp];
                    hh[e] = __float2half_rn(hv);
                }
                *reinterpret_cast<uint32_t*>(g_A2 + (size_t)row * KPAD + ch * 40 + h2) =
                    *reinterpret_cast<uint32_t*>(hh);
            }
            __syncthreads();
        }
    } else if (MODE == 2) {
#pragma unroll
        for (int mt = 0; mt < 4; mt++)
#pragma unroll
            for (int half = 0; half < 2; half++) {
                int row = m0 + wm * 64 + mt * 16 + g + half * 8;
#pragma unroll
                for (int nt = 0; nt < 4; nt++) {
                    int colL = wn * 32 + nt * 8 + tg * 2;
                    int col = n0 + colL;
                    float2 u = *reinterpret_cast<const float2*>(
                        aux2 + (size_t)row * OUT_HID + col);
                    float t0 = fmaxf(c[mt][nt][2 * half + 0] + biasS[colL], 0.f);
                    float t1 = fmaxf(c[mt][nt][2 * half + 1] + biasS[colL + 1], 0.f);
                    __half hh[2];
                    hh[0] = __float2half_rn((u.x > 0.65f) ? t0 * (1.0f / 0.35f) : 0.f);
                    hh[1] = __float2half_rn((u.y > 0.65f) ? t1 * (1.0f / 0.35f) : 0.f);
                    *reinterpret_cast<uint32_t*>(g_O1 + (size_t)row * OUT_HID + col) =
                        *reinterpret_cast<uint32_t*>(hh);
                }
            }
    } else {  // MODE 3: n = s*8+o; warp covers s = wn*4+nt, o = tg*2,+1
#pragma unroll
        for (int mt = 0; mt < 4; mt++) {
#pragma unroll
            for (int half = 0; half < 2; half++) {
                int row = m0 + wm * 64 + mt * 16 + g + half * 8;
                int b = row & (B_DIM - 1);
                int j = row >> 12;
                float2 iv = *reinterpret_cast<const float2*>(g_inno + b * O_DIM + tg * 2);
#pragma unroll
                for (int nt = 0; nt < 4; nt++) {
                    int colL = wn * 32 + nt * 8 + tg * 2;
                    float v = (c[mt][nt][2 * half + 0] + biasS[colL]) * iv.x
                            + (c[mt][nt][2 * half + 1] + biasS[colL + 1]) * iv.y;
                    v += __shfl_xor_sync(0xffffffffu, v, 1);
                    v += __shfl_xor_sync(0xffffffffu, v, 2);
                    if (tg == 0) {
                        int s = wn * 4 + nt;
                        ens[(size_t)b * (J_DIM * S_DIM) + j * S_DIM + s] =
                            g_xpred[b * S_DIM + s] + v;
                    }
                }
            }
        }
    }
}

// ---------------- mean / unbiased var over J --------------------------------
__global__ void reduce_kernel(const float* __restrict__ ens, float* __restrict__ out) {
    int idx = blockIdx.x * blockDim.x + threadIdx.x;
    if (idx >= B_DIM * S_DIM) return;
    int b = idx >> 4, s = idx & 15;
    const float* p = ens + (size_t)b * (J_DIM * S_DIM) + s;
    float v[J_DIM], sum = 0.f;
#pragma unroll
    for (int j = 0; j < J_DIM; j++) { v[j] = p[j * S_DIM]; sum += v[j]; }
    float mean = sum * (1.0f / J_DIM);
    float var = 0.f;
#pragma unroll
    for (int j = 0; j < J_DIM; j++) { float d = v[j] - mean; var = fmaf(d, d, var); }
    out[idx] = mean;
    out[B_DIM * S_DIM + idx] = var * (1.0f / (J_DIM - 1));
}

// ---------------- launcher --------------------------------------------------
extern "C" void kernel_launch(void* const* d_in, const int* in_sizes, int n_in,
                              void* d_out, int out_size) {
    const float* y_t    = (const float*)d_in[0];
    const float* xprev  = (const float*)d_in[1];
    const float* F      = (const float*)d_in[2];
    const float* H      = (const float*)d_in[3];
    const float* W_fc   = (const float*)d_in[4];
    const float* b_fc   = (const float*)d_in[5];
    const float* W_ih   = (const float*)d_in[6];
    const float* W_hh   = (const float*)d_in[7];
    const float* b_ih   = (const float*)d_in[8];
    const float* b_hh   = (const float*)d_in[9];
    const float* W_out1 = (const float*)d_in[10];
    const float* b_out1 = (const float*)d_in[11];
    const float* W_out2 = (const float*)d_in[12];
    const float* b_out2 = (const float*)d_in[13];
    const float* h_init = (const float*)d_in[14];
    const float* u1     = (const float*)d_in[15];
    const float* u2     = (const float*)d_in[16];

    float* out = (float*)d_out;
    float* ens = out + 2 * B_DIM * S_DIM + 1;

    cudaFuncSetAttribute((const void*)gemm_mma<1>, cudaFuncAttributeMaxDynamicSharedMemorySize, GEMM_SMEM);
    cudaFuncSetAttribute((const void*)gemm_mma<2>, cudaFuncAttributeMaxDynamicSharedMemorySize, GEMM_SMEM);
    cudaFuncSetAttribute((const void*)gemm_mma<3>, cudaFuncAttributeMaxDynamicSharedMemorySize, GEMM_SMEM);

    gh_kernel<<<3, 256>>>(W_hh, b_hh, h_init, out);
    bprep_kernel<<<3, 256>>>(b_ih);
    prep_kernel<<<B_DIM, 256>>>(y_t, xprev, F, H, W_fc, b_fc);
    convW_kernel<<<(768 * KPAD + 512 * KPAD + 128 * 512 + 255) / 256, 256>>>(W_ih, W_out1, W_out2);
    conv1_kernel<<<(JB * 32) / 256, 256>>>(u1);

    // G1 + GRU fused epilogue -> g_A2
    gemm_mma<1><<<dim3(6, JB / 128), 256, GEMM_SMEM>>>(nullptr, h_init, nullptr);

    // G2: O1 = fp16(relu(A2 @ Wo1^T + b) * mask2)
    gemm_mma<2><<<dim3(4, JB / 128), 256, GEMM_SMEM>>>(b_out1, u2, nullptr);

    // G3: ensemble = xpred + (O1 @ Wo2^T + b2) . inno
    gemm_mma<3><<<dim3(1, JB / 128), 256, GEMM_SMEM>>>(b_out2, nullptr, ens);

    reduce_kernel<<<(B_DIM * S_DIM) / 256, 256>>>(ens, out);
}